// round 15
// baseline (speedup 1.0000x reference)
#include <cuda_runtime.h>
#include <cuda_fp16.h>

// ---------------------------------------------------------------------------
// GAT 3-layer GNN, N=50000 nodes, E=800000 edges (+50000 self loops),
// dims 256->128->128->128, heads=1, leaky_relu(0.2), global mean pool to 16.
// R13: stream fork-join (GEMM-0 overlaps CSR build); W fp32 converted
//      in-flight inside GEMM (no prep conversion); packed-pair agg smem with
//      unroll-8 gather; ticketed pool tail keeps scratch-zero invariant.
// ---------------------------------------------------------------------------

#define N_NODES 50000
#define N_GRAPHS 16
#define E_EDGES 800000
#define E_TOT   (E_EDGES + N_NODES)
#define IN_DIM  256
#define HID     128
#define NEG_SLOPE 0.2f

// -------------------- device scratch (no allocations allowed) --------------
// Invariant: g_deg, g_pool, g_pcnt, g_tick are ZERO on entry to kernel_launch
// (zero-initialized at module load; re-zeroed by the k_pool tail each call).
__device__ __half2 g_hh[N_NODES * (HID / 2)];              // h (pre-agg) fp16
__device__ __half2 g_fh[N_NODES * (HID / 2)];              // feat fp16
__device__ float   g_als[N_NODES];
__device__ float   g_ald[N_NODES];
__device__ int     g_rowptr[N_NODES + 1];
__device__ int     g_deg[N_NODES];
__device__ int     g_cursor[N_NODES];
__device__ int     g_csrc[E_TOT];
__device__ float   g_pool[N_GRAPHS * HID];
__device__ float   g_pcnt[N_GRAPHS];
__device__ int     g_tick;

// -------------------- helpers ----------------------------------------------
__device__ __forceinline__ uint4 f8_to_h8(float4 a, float4 b) {
    __half2 h0 = __floats2half2_rn(a.x, a.y);
    __half2 h1 = __floats2half2_rn(a.z, a.w);
    __half2 h2 = __floats2half2_rn(b.x, b.y);
    __half2 h3 = __floats2half2_rn(b.z, b.w);
    uint4 u;
    u.x = *(unsigned*)&h0; u.y = *(unsigned*)&h1;
    u.z = *(unsigned*)&h2; u.w = *(unsigned*)&h3;
    return u;
}

// -------------------- degree count (8 edges/thread) -------------------------
#define EV8 (E_EDGES / 8)              // 100,000

__global__ void k_count(const int* __restrict__ ei) {
    int i = blockIdx.x * blockDim.x + threadIdx.x;
    if (i < EV8) {
        const int4* d4 = (const int4*)(ei + E_EDGES);
        int4 a = d4[2 * i], b = d4[2 * i + 1];
        atomicAdd(&g_deg[a.x], 1); atomicAdd(&g_deg[a.y], 1);
        atomicAdd(&g_deg[a.z], 1); atomicAdd(&g_deg[a.w], 1);
        atomicAdd(&g_deg[b.x], 1); atomicAdd(&g_deg[b.y], 1);
        atomicAdd(&g_deg[b.z], 1); atomicAdd(&g_deg[b.w], 1);
    } else {
        int j = i - EV8;
        if (j < N_NODES) atomicAdd(&g_deg[j], 1);   // self loop
    }
}

// -------------------- exclusive scan of degrees -----------------------------
__global__ void k_scan() {
    __shared__ int s[1024];
    const int t = threadIdx.x;
    const int CH = (N_NODES + 1023) / 1024;   // 49
    const int base = t * CH;
    int sum = 0;
    for (int i = 0; i < CH; i++) {
        int v = base + i;
        if (v < N_NODES) sum += g_deg[v];
    }
    s[t] = sum;
    __syncthreads();
    for (int off = 1; off < 1024; off <<= 1) {
        int v = (t >= off) ? s[t - off] : 0;
        __syncthreads();
        s[t] += v;
        __syncthreads();
    }
    int run = (t > 0) ? s[t - 1] : 0;
    for (int i = 0; i < CH; i++) {
        int v = base + i;
        if (v < N_NODES) {
            g_rowptr[v] = run;
            g_cursor[v] = run;
            run += g_deg[v];
        }
    }
    if (t == 1023) g_rowptr[N_NODES] = s[1023];
}

// -------------------- scatter (8 edges/thread) ------------------------------
__global__ void k_scatter(const int* __restrict__ ei) {
    int i = blockIdx.x * blockDim.x + threadIdx.x;
    if (i < EV8) {
        const int4* s4 = (const int4*)ei;
        const int4* d4 = (const int4*)(ei + E_EDGES);
        int4 sa = s4[2 * i], sb = s4[2 * i + 1];
        int4 da = d4[2 * i], db = d4[2 * i + 1];
        g_csrc[atomicAdd(&g_cursor[da.x], 1)] = sa.x;
        g_csrc[atomicAdd(&g_cursor[da.y], 1)] = sa.y;
        g_csrc[atomicAdd(&g_cursor[da.z], 1)] = sa.z;
        g_csrc[atomicAdd(&g_cursor[da.w], 1)] = sa.w;
        g_csrc[atomicAdd(&g_cursor[db.x], 1)] = sb.x;
        g_csrc[atomicAdd(&g_cursor[db.y], 1)] = sb.y;
        g_csrc[atomicAdd(&g_cursor[db.z], 1)] = sb.z;
        g_csrc[atomicAdd(&g_cursor[db.w], 1)] = sb.w;
    } else {
        int j = i - EV8;
        if (j < N_NODES) g_csrc[atomicAdd(&g_cursor[j], 1)] = j;  // self loop
    }
}

// -------------------- tensor-core GEMM + fused attention logits ------------
// h[N,128] = A[N,K] @ W[K,128] (fp16 mma, fp32 accum) -> g_hh fp16 + logits.
// AF32: A is fp32, converted while staging. W is ALWAYS fp32, converted
// while staging (bit-identical to a separate conversion pass).
__device__ __forceinline__ void mma16816(float* c, const unsigned* a,
                                         unsigned b0, unsigned b1) {
    asm volatile(
        "mma.sync.aligned.m16n8k16.row.col.f32.f16.f16.f32 "
        "{%0,%1,%2,%3}, {%4,%5,%6,%7}, {%8,%9}, {%0,%1,%2,%3};"
        : "+f"(c[0]), "+f"(c[1]), "+f"(c[2]), "+f"(c[3])
        : "r"(a[0]), "r"(a[1]), "r"(a[2]), "r"(a[3]), "r"(b0), "r"(b1));
}

template <int AF32>
__global__ __launch_bounds__(256) void k_gemm(const __half* __restrict__ Ah,
                                              const float* __restrict__ Af,
                                              const float* __restrict__ Wf,
                                              const float* __restrict__ a_s,
                                              const float* __restrict__ a_d,
                                              int K) {
    __shared__ __align__(16) __half sA[128 * 40];   // stride 40 (pad 8)
    __shared__ __align__(16) __half sB[32 * 136];   // stride 136 (pad 8)
    __shared__ float s_red[2][2][128];
    const int tid    = threadIdx.x;
    const int lane   = tid & 31;
    const int wid    = tid >> 5;
    const int warp_m = wid & 3;
    const int warp_n = wid >> 2;
    const int block_row = blockIdx.x * 128;

    int arow[2], ako[2], bkr[2], bno[2];
    #pragma unroll
    for (int l = 0; l < 2; l++) {
        int ch = tid + l * 256;
        arow[l] = ch >> 2;  ako[l] = (ch & 3) * 8;
        bkr[l]  = ch >> 4;  bno[l] = (ch & 15) * 8;
    }

    float c[2][8][4];
    #pragma unroll
    for (int mt = 0; mt < 2; mt++)
        #pragma unroll
        for (int nt = 0; nt < 8; nt++)
            #pragma unroll
            for (int q = 0; q < 4; q++) c[mt][nt][q] = 0.f;

    // prefetch tile 0 (A per AF32; W fp32 -> fp16 in-flight)
    uint4 pa[2], pb[2];
    #pragma unroll
    for (int l = 0; l < 2; l++) {
        int grow = block_row + arow[l];
        if (AF32) {
            float4 f0 = make_float4(0.f, 0.f, 0.f, 0.f), f1 = f0;
            if (grow < N_NODES) {
                f0 = *(const float4*)&Af[(size_t)grow * K + ako[l]];
                f1 = *(const float4*)&Af[(size_t)grow * K + ako[l] + 4];
            }
            pa[l] = f8_to_h8(f0, f1);
        } else {
            pa[l] = make_uint4(0u, 0u, 0u, 0u);
            if (grow < N_NODES)
                pa[l] = *(const uint4*)&Ah[(size_t)grow * K + ako[l]];
        }
        {
            const float* wp = &Wf[(size_t)bkr[l] * HID + bno[l]];
            pb[l] = f8_to_h8(*(const float4*)wp, *(const float4*)(wp + 4));
        }
    }

    for (int k0 = 0; k0 < K; k0 += 32) {
        #pragma unroll
        for (int l = 0; l < 2; l++) {
            *(uint4*)&sA[arow[l] * 40 + ako[l]]  = pa[l];
            *(uint4*)&sB[bkr[l] * 136 + bno[l]] = pb[l];
        }
        __syncthreads();
        if (k0 + 32 < K) {   // prefetch next tile into regs (overlaps MMAs)
            #pragma unroll
            for (int l = 0; l < 2; l++) {
                int grow = block_row + arow[l];
                if (AF32) {
                    float4 f0 = make_float4(0.f, 0.f, 0.f, 0.f), f1 = f0;
                    if (grow < N_NODES) {
                        f0 = *(const float4*)&Af[(size_t)grow * K + k0 + 32 + ako[l]];
                        f1 = *(const float4*)&Af[(size_t)grow * K + k0 + 36 + ako[l]];
                    }
                    pa[l] = f8_to_h8(f0, f1);
                } else {
                    pa[l] = make_uint4(0u, 0u, 0u, 0u);
                    if (grow < N_NODES)
                        pa[l] = *(const uint4*)&Ah[(size_t)grow * K + k0 + 32 + ako[l]];
                }
                const float* wp = &Wf[(size_t)(k0 + 32 + bkr[l]) * HID + bno[l]];
                pb[l] = f8_to_h8(*(const float4*)wp, *(const float4*)(wp + 4));
            }
        }
        #pragma unroll
        for (int ks = 0; ks < 2; ks++) {
            unsigned af[2][4];
            #pragma unroll
            for (int mt = 0; mt < 2; mt++) {
                unsigned sa = (unsigned)__cvta_generic_to_shared(
                    &sA[(warp_m * 32 + mt * 16 + (lane & 15)) * 40 +
                        ks * 16 + (lane >> 4) * 8]);
                asm volatile(
                    "ldmatrix.sync.aligned.m8n8.x4.shared.b16 {%0,%1,%2,%3}, [%4];"
                    : "=r"(af[mt][0]), "=r"(af[mt][1]),
                      "=r"(af[mt][2]), "=r"(af[mt][3]) : "r"(sa));
            }
            #pragma unroll
            for (int np = 0; np < 4; np++) {
                unsigned b0, b1, b2, b3;
                unsigned sb = (unsigned)__cvta_generic_to_shared(
                    &sB[(ks * 16 + ((lane >> 3) & 1) * 8 + (lane & 7)) * 136 +
                        warp_n * 64 + np * 16 + (lane >> 4) * 8]);
                asm volatile(
                    "ldmatrix.sync.aligned.m8n8.x4.trans.shared.b16 "
                    "{%0,%1,%2,%3}, [%4];"
                    : "=r"(b0), "=r"(b1), "=r"(b2), "=r"(b3) : "r"(sb));
                #pragma unroll
                for (int mt = 0; mt < 2; mt++) {
                    mma16816(c[mt][2 * np],     af[mt], b0, b1);
                    mma16816(c[mt][2 * np + 1], af[mt], b2, b3);
                }
            }
        }
        __syncthreads();
    }

    // ---- epilogue: store h fp16 + fused attention-logit reduction ----
    float2 as2[8], ad2[8];
    #pragma unroll
    for (int nt = 0; nt < 8; nt++) {
        int n0 = warp_n * 64 + nt * 8 + (lane & 3) * 2;
        as2[nt] = *(const float2*)&a_s[n0];
        ad2[nt] = *(const float2*)&a_d[n0];
    }
    float ps[2][2] = {{0.f, 0.f}, {0.f, 0.f}};
    float pd[2][2] = {{0.f, 0.f}, {0.f, 0.f}};
    #pragma unroll
    for (int mt = 0; mt < 2; mt++) {
        int r0 = block_row + warp_m * 32 + mt * 16 + (lane >> 2);
        #pragma unroll
        for (int nt = 0; nt < 8; nt++) {
            float* cc = c[mt][nt];
            int hcol = warp_n * 32 + nt * 4 + (lane & 3);
            if (r0 < N_NODES)
                g_hh[(size_t)r0 * 64 + hcol] = __floats2half2_rn(cc[0], cc[1]);
            if (r0 + 8 < N_NODES)
                g_hh[(size_t)(r0 + 8) * 64 + hcol] = __floats2half2_rn(cc[2], cc[3]);
            ps[mt][0] += cc[0] * as2[nt].x + cc[1] * as2[nt].y;
            ps[mt][1] += cc[2] * as2[nt].x + cc[3] * as2[nt].y;
            pd[mt][0] += cc[0] * ad2[nt].x + cc[1] * ad2[nt].y;
            pd[mt][1] += cc[2] * ad2[nt].x + cc[3] * ad2[nt].y;
        }
    }
    #pragma unroll
    for (int o = 1; o <= 2; o <<= 1) {
        #pragma unroll
        for (int mt = 0; mt < 2; mt++)
            #pragma unroll
            for (int rh = 0; rh < 2; rh++) {
                ps[mt][rh] += __shfl_xor_sync(0xFFFFFFFFu, ps[mt][rh], o);
                pd[mt][rh] += __shfl_xor_sync(0xFFFFFFFFu, pd[mt][rh], o);
            }
    }
    if ((lane & 3) == 0) {
        #pragma unroll
        for (int mt = 0; mt < 2; mt++)
            #pragma unroll
            for (int rh = 0; rh < 2; rh++) {
                int row = warp_m * 32 + mt * 16 + rh * 8 + (lane >> 2);
                s_red[0][warp_n][row] = ps[mt][rh];
                s_red[1][warp_n][row] = pd[mt][rh];
            }
    }
    __syncthreads();
    if (tid < 128) {
        int grow = block_row + tid;
        if (grow < N_NODES) {
            g_als[grow] = s_red[0][0][tid] + s_red[0][1][tid];
            g_ald[grow] = s_red[1][0][tid] + s_red[1][1][tid];
        }
    }
}

// -------------------- softmax aggregation (one warp per dst node) ----------
__global__ __launch_bounds__(256) void k_agg(const float* __restrict__ bias,
                                             int last) {
    __shared__ uint2 pr[8][128];   // .x = src index, .y = coef bits
    const int wid  = threadIdx.x >> 5;
    const int lane = threadIdx.x & 31;
    const int v = blockIdx.x * 8 + wid;
    if (v >= N_NODES) return;
    const int beg = g_rowptr[v];
    const int end = g_rowptr[v + 1];
    const int deg = end - beg;
    const float adv = g_ald[v];

    float m = -1e30f, zpart = 0.f;
    float4 acc = make_float4(0.f, 0.f, 0.f, 0.f);

    if (deg <= 128) {
        for (int i = lane; i < deg; i += 32) {
            int s = g_csrc[beg + i];
            float x = g_als[s] + adv;
            x = (x > 0.f) ? x : NEG_SLOPE * x;
            pr[wid][i] = make_uint2((unsigned)s, __float_as_uint(x));
            m = fmaxf(m, x);
        }
        #pragma unroll
        for (int o = 16; o; o >>= 1) m = fmaxf(m, __shfl_xor_sync(0xFFFFFFFFu, m, o));
        for (int i = lane; i < deg; i += 32) {   // same lane re-reads own entries
            float p = __expf(__uint_as_float(pr[wid][i].y) - m);
            pr[wid][i].y = __float_as_uint(p);
            zpart += p;
        }
        __syncwarp();
        #pragma unroll 8
        for (int i = 0; i < deg; i++) {
            uint2 q = pr[wid][i];
            float p = __uint_as_float(q.y);
            uint2 raw = *(const uint2*)&g_hh[(size_t)q.x * (HID / 2) + lane * 2];
            float2 h0 = __half22float2(*(__half2*)&raw.x);
            float2 h1 = __half22float2(*(__half2*)&raw.y);
            acc.x += p * h0.x; acc.y += p * h0.y;
            acc.z += p * h1.x; acc.w += p * h1.y;
        }
    } else {
        for (int e = beg + lane; e < end; e += 32) {
            float x = g_als[g_csrc[e]] + adv;
            x = (x > 0.f) ? x : NEG_SLOPE * x;
            m = fmaxf(m, x);
        }
        #pragma unroll
        for (int o = 16; o; o >>= 1) m = fmaxf(m, __shfl_xor_sync(0xFFFFFFFFu, m, o));
        for (int cb = beg; cb < end; cb += 128) {
            int cnt = min(128, end - cb);
            for (int i = lane; i < cnt; i += 32) {
                int s = g_csrc[cb + i];
                float x = g_als[s] + adv;
                x = (x > 0.f) ? x : NEG_SLOPE * x;
                float p = __expf(x - m);
                pr[wid][i] = make_uint2((unsigned)s, __float_as_uint(p));
                zpart += p;
            }
            __syncwarp();
            #pragma unroll 8
            for (int i = 0; i < cnt; i++) {
                uint2 q = pr[wid][i];
                float p = __uint_as_float(q.y);
                uint2 raw = *(const uint2*)&g_hh[(size_t)q.x * (HID / 2) + lane * 2];
                float2 h0 = __half22float2(*(__half2*)&raw.x);
                float2 h1 = __half22float2(*(__half2*)&raw.y);
                acc.x += p * h0.x; acc.y += p * h0.y;
                acc.z += p * h1.x; acc.w += p * h1.y;
            }
            __syncwarp();
        }
    }
    #pragma unroll
    for (int o = 16; o; o >>= 1) zpart += __shfl_xor_sync(0xFFFFFFFFu, zpart, o);
    const float inv = 1.f / zpart;   // self-loop guarantees zpart > 0

    float4 bb = *(const float4*)&bias[lane * 4];
    acc.x = acc.x * inv + bb.x;
    acc.y = acc.y * inv + bb.y;
    acc.z = acc.z * inv + bb.z;
    acc.w = acc.w * inv + bb.w;
    if (!last) {
        acc.x = fmaxf(acc.x, 0.f); acc.y = fmaxf(acc.y, 0.f);
        acc.z = fmaxf(acc.z, 0.f); acc.w = fmaxf(acc.w, 0.f);
    }
    __half2 f0 = __floats2half2_rn(acc.x, acc.y);
    __half2 f1 = __floats2half2_rn(acc.z, acc.w);
    uint2 u;
    u.x = *(unsigned*)&f0;
    u.y = *(unsigned*)&f1;
    *(uint2*)&g_fh[(size_t)v * (HID / 2) + lane * 2] = u;
}

// ---------- global mean pool + final divide + scratch re-zero (tail) -------
__global__ __launch_bounds__(256) void k_pool(const int* __restrict__ batch,
                                              float* __restrict__ out) {
    __shared__ float s[N_GRAPHS * HID];
    __shared__ float sc[N_GRAPHS];
    __shared__ int isLast;
    const int tid = threadIdx.x;
    for (int i = tid; i < N_GRAPHS * HID; i += 256) s[i] = 0.f;
    if (tid < N_GRAPHS) sc[tid] = 0.f;
    __syncthreads();
    const int wid = tid >> 5, lane = tid & 31;
    for (int v = blockIdx.x * 8 + wid; v < N_NODES; v += gridDim.x * 8) {
        int g = batch[v];
        uint2 raw = *(const uint2*)&g_fh[(size_t)v * (HID / 2) + lane * 2];
        float2 h0 = __half22float2(*(__half2*)&raw.x);
        float2 h1 = __half22float2(*(__half2*)&raw.y);
        float* d = &s[g * HID + lane * 4];
        atomicAdd(d + 0, h0.x); atomicAdd(d + 1, h0.y);
        atomicAdd(d + 2, h1.x); atomicAdd(d + 3, h1.y);
        if (lane == 0) atomicAdd(&sc[g], 1.f);
    }
    __syncthreads();
    for (int i = tid; i < N_GRAPHS * HID; i += 256) atomicAdd(&g_pool[i], s[i]);
    if (tid < N_GRAPHS) atomicAdd(&g_pcnt[tid], sc[tid]);

    // ticketed tail: last block finalizes output and re-zeroes scratch
    __threadfence();
    __syncthreads();
    if (tid == 0) isLast = (atomicAdd(&g_tick, 1) == (int)gridDim.x - 1);
    __syncthreads();
    if (isLast) {
        for (int i = tid; i < N_GRAPHS * HID; i += 256)
            out[i] = g_pool[i] / fmaxf(g_pcnt[i / HID], 1.f);
        __syncthreads();
        for (int i = tid; i < N_GRAPHS * HID; i += 256) g_pool[i] = 0.f;
        if (tid < N_GRAPHS) g_pcnt[tid] = 0.f;
        for (int i = tid; i < N_NODES; i += 256) g_deg[i] = 0;
        if (tid == 0) g_tick = 0;
    }
}

// -------------------- launch -----------------------------------------------
extern "C" void kernel_launch(void* const* d_in, const int* in_sizes, int n_in,
                              void* d_out, int out_size) {
    const float* x     = (const float*)d_in[0];
    const int*   ei    = (const int*)d_in[1];
    const int*   batch = (const int*)d_in[2];
    const float* W[3]  = { (const float*)d_in[3], (const float*)d_in[7],  (const float*)d_in[11] };
    const float* AS[3] = { (const float*)d_in[4], (const float*)d_in[8],  (const float*)d_in[12] };
    const float* AD[3] = { (const float*)d_in[5], (const float*)d_in[9],  (const float*)d_in[13] };
    const float* B[3]  = { (const float*)d_in[6], (const float*)d_in[10], (const float*)d_in[14] };
    float* out = (float*)d_out;

    __half2* d_fh;
    cudaGetSymbolAddress((void**)&d_fh, g_fh);

    const int CB = (EV8 + N_NODES + 255) / 256;        // 586
    const int GB = (N_NODES + 127) / 128;              // 391
    const int NB = (N_NODES + 7) / 8;                  // 6250

    // fork: GEMM-0 (depends only on x, W0) overlaps the CSR build chain.
    cudaStream_t s2;
    cudaStreamCreate(&s2);
    cudaEvent_t evFork, evG0;
    cudaEventCreateWithFlags(&evFork, cudaEventDisableTiming);
    cudaEventCreateWithFlags(&evG0, cudaEventDisableTiming);

    cudaEventRecord(evFork, 0);
    cudaStreamWaitEvent(s2, evFork, 0);
    k_gemm<1><<<GB, 256, 0, s2>>>(nullptr, x, W[0], AS[0], AD[0], IN_DIM);
    cudaEventRecord(evG0, s2);

    // CSR build on the main stream (deg pre-zeroed by previous call's tail)
    k_count<<<CB, 256>>>(ei);
    k_scan<<<1, 1024>>>();
    k_scatter<<<CB, 256>>>(ei);

    // join: agg0 needs both CSR and GEMM-0
    cudaStreamWaitEvent(0, evG0, 0);
    k_agg<<<NB, 256>>>(B[0], /*last=*/0);

    // layer 1
    k_gemm<0><<<GB, 256>>>((const __half*)d_fh, nullptr, W[1], AS[1], AD[1], HID);
    k_agg<<<NB, 256>>>(B[1], /*last=*/0);
    // layer 2
    k_gemm<0><<<GB, 256>>>((const __half*)d_fh, nullptr, W[2], AS[2], AD[2], HID);
    k_agg<<<NB, 256>>>(B[2], /*last=*/1);

    // pool + final + scratch re-zero (ticketed tail block)
    k_pool<<<148, 256>>>(batch, out);
}